// round 13
// baseline (speedup 1.0000x reference)
#include <cuda_runtime.h>
#include <cuda_fp16.h>
#include <cstdint>

#define BB 4
#define SS 2048
#define HH 8
#define DD 64
#define EE 512
#define BH (BB*HH)

// Scratch (allocation-free: __device__ globals)
__device__ __half g_Qh[BH*SS*DD];   // [b,h,s,d] Q' = x @ (C*Wq^T Wk), fp16
__device__ __half g_Xt[BH*DD*SS];   // [b,h,d,s] x transposed (MMA1 B operand)
__device__ __half g_Xh[BH*SS*DD];   // [b,h,s,d] raw x fp16 (MMA2 B operand)
__device__ __half g_MT[DD*DD];      // M^T: MT[b][a] = C*sum_e Wq[e][a]Wk[e][b]
__device__ __half g_AOh[BB*SS*EE];  // attention output fp16 (pre-Wo2)
__device__ __half g_WoT[EE*EE];     // Wo2[k][e] fp16 (Wv folded into Wo)

// ============================ helpers ======================================
__device__ __forceinline__ uint32_t smem_u32(const void* p) {
    uint32_t a;
    asm("{ .reg .u64 t; cvta.to.shared.u64 t, %1; cvt.u32.u64 %0, t; }"
        : "=r"(a) : "l"(p));
    return a;
}
__device__ __forceinline__ uint32_t h2ex2(uint32_t x) {
    uint32_t r;
    asm("ex2.approx.f16x2 %0, %1;" : "=r"(r) : "r"(x));
    return r;
}
// fp16 inputs, fp32 accum
__device__ __forceinline__ void mma_f16(float* c, const uint32_t* a,
                                        uint32_t b0, uint32_t b1) {
    asm volatile("mma.sync.aligned.m16n8k16.row.col.f32.f16.f16.f32 "
        "{%0,%1,%2,%3}, {%4,%5,%6,%7}, {%8,%9}, {%0,%1,%2,%3};"
        : "+f"(c[0]), "+f"(c[1]), "+f"(c[2]), "+f"(c[3])
        : "r"(a[0]), "r"(a[1]), "r"(a[2]), "r"(a[3]), "r"(b0), "r"(b1));
}
// fp16 inputs, fp16 accum (C/D = 2 x b32 packed half2)
__device__ __forceinline__ void mma_f16f16(uint32_t* c, const uint32_t* a,
                                           uint32_t b0, uint32_t b1) {
    asm volatile("mma.sync.aligned.m16n8k16.row.col.f16.f16.f16.f16 "
        "{%0,%1}, {%2,%3,%4,%5}, {%6,%7}, {%0,%1};"
        : "+r"(c[0]), "+r"(c[1])
        : "r"(a[0]), "r"(a[1]), "r"(a[2]), "r"(a[3]), "r"(b0), "r"(b1));
}
__device__ __forceinline__ void ldmx4(uint32_t* r, uint32_t addr) {
    asm volatile("ldmatrix.sync.aligned.m8n8.x4.shared.b16 {%0,%1,%2,%3}, [%4];"
        : "=r"(r[0]), "=r"(r[1]), "=r"(r[2]), "=r"(r[3]) : "r"(addr));
}
__device__ __forceinline__ void ldmx4t(uint32_t* r, uint32_t addr) {
    asm volatile("ldmatrix.sync.aligned.m8n8.x4.trans.shared.b16 {%0,%1,%2,%3}, [%4];"
        : "=r"(r[0]), "=r"(r[1]), "=r"(r[2]), "=r"(r[3]) : "r"(addr));
}
__device__ __forceinline__ void ldmx2t(uint32_t* r, uint32_t addr) {
    asm volatile("ldmatrix.sync.aligned.m8n8.x2.trans.shared.b16 {%0,%1}, [%2];"
        : "=r"(r[0]), "=r"(r[1]) : "r"(addr));
}
__device__ __forceinline__ void cp16(uint32_t dst, const void* src) {
    asm volatile("cp.async.cg.shared.global [%0], [%1], 16;"
                 :: "r"(dst), "l"(src));
}
#define CP_COMMIT() asm volatile("cp.async.commit_group;" ::: "memory")
#define CP_WAIT0()  asm volatile("cp.async.wait_group 0;" ::: "memory")
#define CP_WAIT1()  asm volatile("cp.async.wait_group 1;" ::: "memory")

// ---------------------------------------------------------------------------
// Kernel P1: MT[b][a] = C * sum_e Wq[e][a] * Wk[e][b]. 16 blocks (parallel).
// ---------------------------------------------------------------------------
__global__ void m_prep_kernel(const float* __restrict__ Wq,
                              const float* __restrict__ Wk)
{
    __shared__ float sq[64*64], sk[64*64];
    const int tid = threadIdx.x;
    for (int i = tid; i < 4096; i += 256) { sq[i] = Wq[i]; sk[i] = Wk[i]; }
    __syncthreads();
    const int idx = blockIdx.x * 256 + tid;
    const int bq = idx >> 6, a = idx & 63;
    float acc = 0.f;
    #pragma unroll 8
    for (int e = 0; e < 64; e++) acc += sq[e*64 + a] * sk[e*64 + bq];
    g_MT[bq*64 + a] = __float2half(acc * 0.18033688011112042f);
}

// ---------------------------------------------------------------------------
// Kernel P2: Wo2[h*64+d][e] = sum_dp Wv[dp][d] * Wo[e][h*64+dp].
// grid (EE/64, HH), block 256. Thread owns fixed d + 16 e-outputs in regs.
// ---------------------------------------------------------------------------
__global__ void wo2_prep_kernel(const float* __restrict__ Wv,
                                const float* __restrict__ Wo)
{
    __shared__ float sv[64*64];      // Wv[dp][d]
    __shared__ float so[64][68];     // so[dp][e] = Wo[e0+e][h*64+dp]
    const int h = blockIdx.y, e0 = blockIdx.x * 64;
    const int tid = threadIdx.x;
    for (int i = tid; i < 4096; i += 256) {
        sv[i] = Wv[i];
        int e = i >> 6, dp = i & 63;
        so[dp][e] = Wo[(size_t)(e0 + e)*EE + h*64 + dp];
    }
    __syncthreads();
    const int d = tid >> 2;
    const int eb = (tid & 3) * 16;
    float acc[16];
    #pragma unroll
    for (int j = 0; j < 16; j++) acc[j] = 0.f;
    #pragma unroll 4
    for (int dp = 0; dp < 64; dp++) {
        float s = sv[dp*64 + d];
        #pragma unroll
        for (int j = 0; j < 16; j++) acc[j] += s * so[dp][eb + j];
    }
    #pragma unroll
    for (int j = 0; j < 16; j++)
        g_WoT[(size_t)(h*64 + d)*EE + e0 + eb + j] = __float2half(acc[j]);
}

// ---------------------------------------------------------------------------
// Kernel 1: x -> fp16 (g_Xh row-major, g_Xt transposed) and Q' = x @ M.
// ---------------------------------------------------------------------------
__global__ __launch_bounds__(256, 2) void proj_kernel(
    const float* __restrict__ X)
{
    __shared__ __half Xh[128*72];
    __shared__ __half Mh[64*72];
    const uint32_t xbase = smem_u32(Xh);

    const int bh = blockIdx.y;
    const int b  = bh >> 3, h = bh & 7;
    const int s0 = blockIdx.x * 128;
    const int tid = threadIdx.x;
    const int wid = tid >> 5, lane = tid & 31;
    const int wq = wid >> 1, we = wid & 1;
    const int R0 = wq * 32, E0 = we * 32;
    const int qr = lane >> 2, qc = lane & 3;

    #pragma unroll
    for (int i = 0; i < 8; i++) {
        int f = tid + 256*i;
        int r = f >> 4, c4 = (f & 15) << 2;
        float4 v = *(const float4*)&X[((size_t)b*SS + s0 + r)*EE + h*DD + c4];
        __half2 h01 = __floats2half2_rn(v.x, v.y);
        __half2 h23 = __floats2half2_rn(v.z, v.w);
        *(__half2*)&Xh[r*72 + c4]     = h01;
        *(__half2*)&Xh[r*72 + c4 + 2] = h23;
        __half* gx = &g_Xh[((size_t)bh*SS + s0 + r)*DD + c4];
        *(__half2*)&gx[0] = h01;
        *(__half2*)&gx[2] = h23;
    }
    #pragma unroll
    for (int i = 0; i < 2; i++) {
        int f = tid + 256*i;
        int r = f >> 3, c8 = (f & 7) << 3;
        *(uint4*)&Mh[r*72 + c8] = *(const uint4*)&g_MT[r*64 + c8];
    }
    __syncthreads();

    // ---- transposed fp16 x: g_Xt[d][s] (via smem tile, coalesced-ish) ----
    {
        const int d = tid >> 2;
        const int sc = (tid & 3) * 32;
        #pragma unroll
        for (int j = 0; j < 4; j++) {
            __half buf[8];
            #pragma unroll
            for (int k = 0; k < 8; k++)
                buf[k] = Xh[(sc + j*8 + k)*72 + d];
            *(uint4*)&g_Xt[((size_t)bh*DD + d)*SS + s0 + sc + j*8] =
                *(uint4*)buf;
        }
    }

    float c[2][4][4];
    #pragma unroll
    for (int m = 0; m < 2; m++)
        #pragma unroll
        for (int n = 0; n < 4; n++)
            #pragma unroll
            for (int r = 0; r < 4; r++) c[m][n][r] = 0.f;

    #pragma unroll
    for (int t = 0; t < 4; t++) {
        uint32_t qa[2][4];
        #pragma unroll
        for (int m = 0; m < 2; m++)
            ldmx4(qa[m], xbase +
                ((uint32_t)(R0 + 16*m + (lane & 15))*72 + t*16 + (lane >> 4)*8)*2);
        #pragma unroll
        for (int n = 0; n < 4; n++) {
            int jj = E0 + n*8 + qr;
            uint32_t b0 = *(const uint32_t*)&Mh[jj*72 + t*16 + qc*2];
            uint32_t b1 = *(const uint32_t*)&Mh[jj*72 + t*16 + qc*2 + 8];
            mma_f16(c[0][n], qa[0], b0, b1);
            mma_f16(c[1][n], qa[1], b0, b1);
        }
    }

    #pragma unroll
    for (int m = 0; m < 2; m++)
        #pragma unroll
        for (int n = 0; n < 4; n++) {
            int e = E0 + n*8 + qc*2;
            int s = s0 + R0 + 16*m + qr;
            *(__half2*)&g_Qh[((size_t)bh*SS + s)*DD + e] =
                __floats2half2_rn(c[m][n][0], c[m][n][1]);
            *(__half2*)&g_Qh[((size_t)bh*SS + s+8)*DD + e] =
                __floats2half2_rn(c[m][n][2], c[m][n][3]);
        }
}

// ---------------------------------------------------------------------------
// Attention stage loader: cp.async Xt chunk ([64][136]) + Xh tile ([128][72]).
// (Ones-columns of the Xh tile, cols 64-71, are constant; written once.)
// ---------------------------------------------------------------------------
__device__ __forceinline__ void load_kv_stage(
    uint32_t kaddr, uint32_t vaddr, int bh, int kt, int tid)
{
    #pragma unroll
    for (int i = 0; i < 4; i++) {
        int f = tid + 256*i;
        int d = f >> 4, c8 = (f & 15) << 3;
        cp16(kaddr + (uint32_t)(d*136 + c8)*2,
             &g_Xt[((size_t)bh*DD + d)*SS + (size_t)kt*128 + c8]);
        int r = f >> 3, v8 = (f & 7) << 3;
        cp16(vaddr + (uint32_t)(r*72 + v8)*2,
             &g_Xh[((size_t)bh*SS + (size_t)kt*128 + r)*DD + v8]);
    }
}

// ---------------------------------------------------------------------------
// Kernel 2: FA2-style attention (R8's measured-fastest config, verbatim).
// CTA: 128 q-rows, 256 thr / 8 warps. Warp = 16 q-rows x full 128 j.
// Q' frags in registers. MMA1 f16-acc via ldmx4t on Xt; ex2 -> MMA2 A-frags.
// MMA2 + lsum f16-acc, flushed to fp32 shadows per kt. 3-stage cp.async,
// 2 CTA/SM. Smem: 3 x (Xt[64][136] + Xh[128][72]) = 105 KB.
// ---------------------------------------------------------------------------
__global__ __launch_bounds__(256, 2) void attn_kernel()
{
    extern __shared__ char smb[];
    const int STG = 17408 + 18432;            // 35840 B per stage

    const int bh = blockIdx.y;
    const int b  = bh >> 3, h = bh & 7;
    const int q0 = blockIdx.x * 128;
    const int tid = threadIdx.x;
    const int wid = tid >> 5, lane = tid & 31;
    const int qr = lane >> 2, qc = lane & 3;
    const int W0 = wid * 16;                  // warp's q-row base
    const uint32_t sbase = smem_u32(smb);
    uint32_t kb[3], vb[3];
    #pragma unroll
    for (int i = 0; i < 3; i++) {
        kb[i] = sbase + i*STG;
        vb[i] = kb[i] + 17408;
    }

    // ---- stage Q' through buffer-0 V region, load A-frags to registers ----
    #pragma unroll
    for (int i = 0; i < 4; i++) {
        int f = tid + 256*i;
        int r = f >> 3, c8 = (f & 7) << 3;
        cp16(vb[0] + (uint32_t)(r*72 + c8)*2,
             &g_Qh[((size_t)bh*SS + q0 + r)*DD + c8]);
    }
    CP_COMMIT(); CP_WAIT0();
    __syncthreads();
    uint32_t qa[4][4];
    #pragma unroll
    for (int t = 0; t < 4; t++)
        ldmx4(qa[t], vb[0] +
            ((uint32_t)(W0 + (lane & 15))*72 + t*16 + (lane >> 4)*8)*2);
    __syncthreads();    // all Q reads done before pipeline overwrites vb[0]

    // ones-columns (Xh cols 64-71) for all three buffers
    if (tid < 128) {
        const uint4 ones = make_uint4(0x00003C00u, 0u, 0u, 0u);
        #pragma unroll
        for (int i = 0; i < 3; i++)
            *(uint4*)(smb + (i*STG + 17408) + (tid*72 + 64)*2) = ones;
    }

    load_kv_stage(kb[0], vb[0], bh, 0, tid); CP_COMMIT();
    load_kv_stage(kb[1], vb[1], bh, 1, tid); CP_COMMIT();

    float o[8][4];
    float oL0 = 0.f, oL1 = 0.f;
    #pragma unroll
    for (int n = 0; n < 8; n++)
        #pragma unroll
        for (int r = 0; r < 4; r++) o[n][r] = 0.f;

    for (int kt = 0; kt < SS/128; kt++) {
        const int cur = kt % 3;
        CP_WAIT1();
        __syncthreads();
        if (kt + 2 < SS/128) {
            const int nxt = (kt + 2) % 3;
            load_kv_stage(kb[nxt], vb[nxt], bh, kt+2, tid);
            CP_COMMIT();
        }

        // f16 accumulators for this kt
        uint32_t o16[8][2], oL16[2];
        #pragma unroll
        for (int n = 0; n < 8; n++) { o16[n][0] = 0u; o16[n][1] = 0u; }
        oL16[0] = 0u; oL16[1] = 0u;

        #pragma unroll
        for (int jc = 0; jc < 8; jc++) {
            // ---- MMA1: S(16q x 16j) over k=64, f16 acc; B via ldmx4t ----
            uint32_t sA[2] = {0u, 0u}, sB[2] = {0u, 0u};
            #pragma unroll
            for (int t = 0; t < 4; t++) {
                uint32_t kr[4];
                ldmx4t(kr, kb[cur] +
                    ((uint32_t)(t*16 + (lane & 15))*136 + jc*16 + (lane >> 4)*8)*2);
                mma_f16f16(sA, qa[t], kr[0], kr[1]);
                mma_f16f16(sB, qa[t], kr[2], kr[3]);
            }
            // ---- P = ex2(S) ----
            uint32_t pa[4];
            pa[0] = h2ex2(sA[0]);
            pa[1] = h2ex2(sA[1]);
            pa[2] = h2ex2(sB[0]);
            pa[3] = h2ex2(sB[1]);

            // ---- MMA2 (f16 acc): O16 += P x ; lsum via ones-column ----
            #pragma unroll
            for (int db = 0; db < 4; db++) {
                uint32_t vr[4];
                ldmx4t(vr, vb[cur] +
                    ((uint32_t)(jc*16 + (lane & 15))*72 + db*16 + (lane >> 4)*8)*2);
                mma_f16f16(o16[db*2],   pa, vr[0], vr[1]);
                mma_f16f16(o16[db*2+1], pa, vr[2], vr[3]);
            }
            uint32_t er[2];
            ldmx2t(er, vb[cur] + ((uint32_t)(jc*16 + (lane & 15))*72 + 64)*2);
            mma_f16f16(oL16, pa, er[0], er[1]);
        }

        // ---- flush f16 partials into fp32 shadows (idle fma pipe) ----
        #pragma unroll
        for (int n = 0; n < 8; n++) {
            float2 lo = __half22float2(*(__half2*)&o16[n][0]);
            float2 hi = __half22float2(*(__half2*)&o16[n][1]);
            o[n][0] += lo.x; o[n][1] += lo.y;
            o[n][2] += hi.x; o[n][3] += hi.y;
        }
        oL0 += __low2float(*(__half2*)&oL16[0]);
        oL1 += __low2float(*(__half2*)&oL16[1]);
    }

    // ---- epilogue: lsum broadcast within quad, normalize, store fp16 ----
    float ls0 = __shfl_sync(0xffffffffu, oL0, lane & ~3);
    float ls1 = __shfl_sync(0xffffffffu, oL1, lane & ~3);
    const float inv0 = 1.f / ls0;
    const float inv1 = 1.f / ls1;
    const int row0 = q0 + W0 + qr;
    __half* d0 = &g_AOh[((size_t)b*SS + row0)*EE + h*DD];
    __half* d1 = d0 + (size_t)8*EE;
    #pragma unroll
    for (int n = 0; n < 8; n++) {
        *(__half2*)&d0[n*8 + 2*qc] = __floats2half2_rn(o[n][0]*inv0, o[n][1]*inv0);
        *(__half2*)&d1[n*8 + 2*qc] = __floats2half2_rn(o[n][2]*inv1, o[n][3]*inv1);
    }
}

// ---------------------------------------------------------------------------
// Kernel 3: out = AO @ Wo2 + bo, fp16 mma, 3-stage cp.async, 2 CTA/SM.
// ---------------------------------------------------------------------------
__global__ __launch_bounds__(256, 2) void outproj_kernel(
    const float* __restrict__ bo, float* __restrict__ out)
{
    extern __shared__ char osmb[];
    const int STG = 18432 + 17408;
    const uint32_t sbase = smem_u32(osmb);
    uint32_t ab[3], wb[3];
    #pragma unroll
    for (int i = 0; i < 3; i++) {
        ab[i] = sbase + i*STG;
        wb[i] = ab[i] + 18432;
    }

    const int r0 = blockIdx.y * 128;
    const int e0 = blockIdx.x * 128;
    const int tid = threadIdx.x;
    const int wid = tid >> 5, lane = tid & 31;
    const int wq = wid >> 1, we = wid & 1;
    const int R0 = wq * 32, E0 = we * 64;
    const int qr = lane >> 2, qc = lane & 3;

    float c[2][8][4];
    #pragma unroll
    for (int m = 0; m < 2; m++)
        #pragma unroll
        for (int n = 0; n < 8; n++)
            #pragma unroll
            for (int r = 0; r < 4; r++) c[m][n][r] = 0.f;

    auto issue = [&](int st, int kc) {
        #pragma unroll
        for (int i = 0; i < 4; i++) {
            int f = tid + 256*i;
            int r = f >> 3, c8 = (f & 7) << 3;
            cp16(ab[st] + (uint32_t)(r*72 + c8)*2,
                 &g_AOh[(size_t)(r0 + r)*EE + kc*64 + c8]);
            int d = f >> 4, w8 = (f & 15) << 3;
            cp16(wb[st] + (uint32_t)(d*136 + w8)*2,
                 &g_WoT[(size_t)(kc*64 + d)*EE + e0 + w8]);
        }
        CP_COMMIT();
    };

    issue(0, 0);
    issue(1, 1);

    for (int kc = 0; kc < 8; kc++) {
        const int cur = kc % 3;
        CP_WAIT1();
        __syncthreads();
        if (kc + 2 < 8) issue((kc + 2) % 3, kc + 2);

        #pragma unroll
        for (int t = 0; t < 4; t++) {
            uint32_t qa[2][4];
            #pragma unroll
            for (int m = 0; m < 2; m++)
                ldmx4(qa[m], ab[cur] +
                    ((uint32_t)(R0 + 16*m + (lane & 15))*72 + t*16 + (lane >> 4)*8)*2);
            #pragma unroll
            for (int db = 0; db < 4; db++) {
                uint32_t wr[4];
                ldmx4t(wr, wb[cur] +
                    ((uint32_t)(t*16 + (lane & 15))*136 + E0 + db*16 + (lane >> 4)*8)*2);
                mma_f16(c[0][db*2],   qa[0], wr[0], wr[1]);
                mma_f16(c[1][db*2],   qa[1], wr[0], wr[1]);
                mma_f16(c[0][db*2+1], qa[0], wr[2], wr[3]);
                mma_f16(c[1][db*2+1], qa[1], wr[2], wr[3]);
            }
        }
    }

    #pragma unroll
    for (int m = 0; m < 2; m++)
        #pragma unroll
        for (int n = 0; n < 8; n++) {
            int e = e0 + E0 + n*8 + qc*2;
            float b0 = bo[e], b1 = bo[e+1];
            int r = r0 + R0 + 16*m + qr;
            *(float2*)&out[(size_t)r*EE + e] =
                make_float2(c[m][n][0] + b0, c[m][n][1] + b1);
            *(float2*)&out[(size_t)(r+8)*EE + e] =
                make_float2(c[m][n][2] + b0, c[m][n][3] + b1);
        }
}

// ---------------------------------------------------------------------------
extern "C" void kernel_launch(void* const* d_in, const int* in_sizes, int n_in,
                              void* d_out, int out_size)
{
    const float* queries = (const float*)d_in[0];
    // d_in[1]/d_in[2] unused: reference derives K and V from queries.
    const float* Wq = (const float*)d_in[3];
    const float* Wk = (const float*)d_in[4];
    const float* Wv = (const float*)d_in[5];
    const float* Wo = (const float*)d_in[6];
    const float* bo = (const float*)d_in[7];
    float* out = (float*)d_out;

    const int ATTN_SMEM = 3 * (17408 + 18432);   // 107520 B
    const int OP_SMEM   = 3 * (18432 + 17408);   // 107520 B
    cudaFuncSetAttribute(attn_kernel,
        cudaFuncAttributeMaxDynamicSharedMemorySize, ATTN_SMEM);
    cudaFuncSetAttribute(outproj_kernel,
        cudaFuncAttributeMaxDynamicSharedMemorySize, OP_SMEM);

    m_prep_kernel<<<16, 256>>>(Wq, Wk);
    wo2_prep_kernel<<<dim3(EE/64, HH), 256>>>(Wv, Wo);
    proj_kernel<<<dim3(SS/128, BH), 256>>>(queries);
    attn_kernel<<<dim3(SS/128, BH), 256, ATTN_SMEM>>>();
    outproj_kernel<<<dim3(EE/128, (BB*SS)/128), 256, OP_SMEM>>>(bo, out);
}

// round 14
// speedup vs baseline: 1.0848x; 1.0848x over previous
#include <cuda_runtime.h>
#include <cuda_fp16.h>
#include <cstdint>

#define BB 4
#define SS 2048
#define HH 8
#define DD 64
#define EE 512
#define BH (BB*HH)

// Scratch (allocation-free: __device__ globals)
__device__ __half g_Qh[BH*SS*DD];   // [b,h,s,d] Q' = x @ (C*Wq^T Wk), fp16
__device__ __half g_Xh[BH*SS*DD];   // [b,h,s,d] raw x fp16 (serves as K and V)
__device__ __half g_MT[DD*DD];      // M^T: MT[b][a] = C*sum_e Wq[e][a]Wk[e][b]
__device__ __half g_AOh[BB*SS*EE];  // attention output fp16 (pre-Wo2)
__device__ __half g_WoT[EE*EE];     // Wo2[k][e] fp16 (Wv folded into Wo)

// ============================ helpers ======================================
__device__ __forceinline__ uint32_t smem_u32(const void* p) {
    uint32_t a;
    asm("{ .reg .u64 t; cvta.to.shared.u64 t, %1; cvt.u32.u64 %0, t; }"
        : "=r"(a) : "l"(p));
    return a;
}
__device__ __forceinline__ uint32_t h2ex2(uint32_t x) {
    uint32_t r;
    asm("ex2.approx.f16x2 %0, %1;" : "=r"(r) : "r"(x));
    return r;
}
__device__ __forceinline__ uint32_t h2add(uint32_t a, uint32_t b) {
    uint32_t r;
    asm("add.f16x2 %0, %1, %2;" : "=r"(r) : "r"(a), "r"(b));
    return r;
}
// fp16 inputs, fp32 accum
__device__ __forceinline__ void mma_f16(float* c, const uint32_t* a,
                                        uint32_t b0, uint32_t b1) {
    asm volatile("mma.sync.aligned.m16n8k16.row.col.f32.f16.f16.f32 "
        "{%0,%1,%2,%3}, {%4,%5,%6,%7}, {%8,%9}, {%0,%1,%2,%3};"
        : "+f"(c[0]), "+f"(c[1]), "+f"(c[2]), "+f"(c[3])
        : "r"(a[0]), "r"(a[1]), "r"(a[2]), "r"(a[3]), "r"(b0), "r"(b1));
}
// fp16 inputs, fp16 accum (C/D = 2 x b32 packed half2)
__device__ __forceinline__ void mma_f16f16(uint32_t* c, const uint32_t* a,
                                           uint32_t b0, uint32_t b1) {
    asm volatile("mma.sync.aligned.m16n8k16.row.col.f16.f16.f16.f16 "
        "{%0,%1}, {%2,%3,%4,%5}, {%6,%7}, {%0,%1};"
        : "+r"(c[0]), "+r"(c[1])
        : "r"(a[0]), "r"(a[1]), "r"(a[2]), "r"(a[3]), "r"(b0), "r"(b1));
}
__device__ __forceinline__ void ldmx4(uint32_t* r, uint32_t addr) {
    asm volatile("ldmatrix.sync.aligned.m8n8.x4.shared.b16 {%0,%1,%2,%3}, [%4];"
        : "=r"(r[0]), "=r"(r[1]), "=r"(r[2]), "=r"(r[3]) : "r"(addr));
}
__device__ __forceinline__ void ldmx4t(uint32_t* r, uint32_t addr) {
    asm volatile("ldmatrix.sync.aligned.m8n8.x4.trans.shared.b16 {%0,%1,%2,%3}, [%4];"
        : "=r"(r[0]), "=r"(r[1]), "=r"(r[2]), "=r"(r[3]) : "r"(addr));
}
__device__ __forceinline__ void cp16(uint32_t dst, const void* src) {
    asm volatile("cp.async.cg.shared.global [%0], [%1], 16;"
                 :: "r"(dst), "l"(src));
}
#define CP_COMMIT() asm volatile("cp.async.commit_group;" ::: "memory")
#define CP_WAIT0()  asm volatile("cp.async.wait_group 0;" ::: "memory")
#define CP_WAIT1()  asm volatile("cp.async.wait_group 1;" ::: "memory")
#define CP_WAIT2()  asm volatile("cp.async.wait_group 2;" ::: "memory")

// ---------------------------------------------------------------------------
// Kernel P1: MT[b][a] = C * sum_e Wq[e][a] * Wk[e][b]. 16 blocks (parallel).
// ---------------------------------------------------------------------------
__global__ void m_prep_kernel(const float* __restrict__ Wq,
                              const float* __restrict__ Wk)
{
    __shared__ float sq[64*64], sk[64*64];
    const int tid = threadIdx.x;
    for (int i = tid; i < 4096; i += 256) { sq[i] = Wq[i]; sk[i] = Wk[i]; }
    __syncthreads();
    const int idx = blockIdx.x * 256 + tid;
    const int bq = idx >> 6, a = idx & 63;
    float acc = 0.f;
    #pragma unroll 8
    for (int e = 0; e < 64; e++) acc += sq[e*64 + a] * sk[e*64 + bq];
    g_MT[bq*64 + a] = __float2half(acc * 0.18033688011112042f);
}

// ---------------------------------------------------------------------------
// Kernel P2: Wo2[h*64+d][e] = sum_dp Wv[dp][d] * Wo[e][h*64+dp].
// grid (EE/64, HH), block 256. Thread owns fixed d + 16 e-outputs in regs.
// ---------------------------------------------------------------------------
__global__ void wo2_prep_kernel(const float* __restrict__ Wv,
                                const float* __restrict__ Wo)
{
    __shared__ float sv[64*64];      // Wv[dp][d]
    __shared__ float so[64][68];     // so[dp][e] = Wo[e0+e][h*64+dp]
    const int h = blockIdx.y, e0 = blockIdx.x * 64;
    const int tid = threadIdx.x;
    for (int i = tid; i < 4096; i += 256) {
        sv[i] = Wv[i];
        int e = i >> 6, dp = i & 63;
        so[dp][e] = Wo[(size_t)(e0 + e)*EE + h*64 + dp];
    }
    __syncthreads();
    const int d = tid >> 2;
    const int eb = (tid & 3) * 16;
    float acc[16];
    #pragma unroll
    for (int j = 0; j < 16; j++) acc[j] = 0.f;
    #pragma unroll 4
    for (int dp = 0; dp < 64; dp++) {
        float s = sv[dp*64 + d];
        #pragma unroll
        for (int j = 0; j < 16; j++) acc[j] += s * so[dp][eb + j];
    }
    #pragma unroll
    for (int j = 0; j < 16; j++)
        g_WoT[(size_t)(h*64 + d)*EE + e0 + eb + j] = __float2half(acc[j]);
}

// ---------------------------------------------------------------------------
// Kernel 1: x -> fp16 (g_Xh) and Q' = x @ M (g_Qh) via fp16 mma.
// ---------------------------------------------------------------------------
__global__ __launch_bounds__(256, 2) void proj_kernel(
    const float* __restrict__ X)
{
    __shared__ __half Xh[128*72];
    __shared__ __half Mh[64*72];
    const uint32_t xbase = smem_u32(Xh);

    const int bh = blockIdx.y;
    const int b  = bh >> 3, h = bh & 7;
    const int s0 = blockIdx.x * 128;
    const int tid = threadIdx.x;
    const int wid = tid >> 5, lane = tid & 31;
    const int wq = wid >> 1, we = wid & 1;
    const int R0 = wq * 32, E0 = we * 32;
    const int qr = lane >> 2, qc = lane & 3;

    #pragma unroll
    for (int i = 0; i < 8; i++) {
        int f = tid + 256*i;
        int r = f >> 4, c4 = (f & 15) << 2;
        float4 v = *(const float4*)&X[((size_t)b*SS + s0 + r)*EE + h*DD + c4];
        __half2 h01 = __floats2half2_rn(v.x, v.y);
        __half2 h23 = __floats2half2_rn(v.z, v.w);
        *(__half2*)&Xh[r*72 + c4]     = h01;
        *(__half2*)&Xh[r*72 + c4 + 2] = h23;
        __half* gx = &g_Xh[((size_t)bh*SS + s0 + r)*DD + c4];
        *(__half2*)&gx[0] = h01;
        *(__half2*)&gx[2] = h23;
    }
    #pragma unroll
    for (int i = 0; i < 2; i++) {
        int f = tid + 256*i;
        int r = f >> 3, c8 = (f & 7) << 3;
        *(uint4*)&Mh[r*72 + c8] = *(const uint4*)&g_MT[r*64 + c8];
    }
    __syncthreads();

    float c[2][4][4];
    #pragma unroll
    for (int m = 0; m < 2; m++)
        #pragma unroll
        for (int n = 0; n < 4; n++)
            #pragma unroll
            for (int r = 0; r < 4; r++) c[m][n][r] = 0.f;

    #pragma unroll
    for (int t = 0; t < 4; t++) {
        uint32_t qa[2][4];
        #pragma unroll
        for (int m = 0; m < 2; m++)
            ldmx4(qa[m], xbase +
                ((uint32_t)(R0 + 16*m + (lane & 15))*72 + t*16 + (lane >> 4)*8)*2);
        #pragma unroll
        for (int n = 0; n < 4; n++) {
            int jj = E0 + n*8 + qr;
            uint32_t b0 = *(const uint32_t*)&Mh[jj*72 + t*16 + qc*2];
            uint32_t b1 = *(const uint32_t*)&Mh[jj*72 + t*16 + qc*2 + 8];
            mma_f16(c[0][n], qa[0], b0, b1);
            mma_f16(c[1][n], qa[1], b0, b1);
        }
    }

    #pragma unroll
    for (int m = 0; m < 2; m++)
        #pragma unroll
        for (int n = 0; n < 4; n++) {
            int e = E0 + n*8 + qc*2;
            int s = s0 + R0 + 16*m + qr;
            *(__half2*)&g_Qh[((size_t)bh*SS + s)*DD + e] =
                __floats2half2_rn(c[m][n][0], c[m][n][1]);
            *(__half2*)&g_Qh[((size_t)bh*SS + s+8)*DD + e] =
                __floats2half2_rn(c[m][n][2], c[m][n][3]);
        }
}

// ---------------------------------------------------------------------------
// Attention stage loader: cp.async one x tile [128][72] (cols 64-71 unused).
// ---------------------------------------------------------------------------
__device__ __forceinline__ void load_x_stage(
    uint32_t xaddr, int bh, int kt, int tid)
{
    #pragma unroll
    for (int i = 0; i < 4; i++) {
        int f = tid + 256*i;
        int r = f >> 3, c8 = (f & 7) << 3;
        cp16(xaddr + (uint32_t)(r*72 + c8)*2,
             &g_Xh[((size_t)bh*SS + (size_t)kt*128 + r)*DD + c8]);
    }
}

// ---------------------------------------------------------------------------
// Kernel 2: attention, K = V = x single tile (R10 measured-best config),
// with (a) lsum computed on the fma pipe from the P fragments (no lsum MMA,
// no ones-column, no ldmx2t) and (b) MMA1 split into 4 independent f16
// accumulator chains (t-halves merged by HADD2) for better ILP.
// CTA: 128 q-rows, 256 thr / 8 warps. Warp = 16 q-rows x full 128 j.
// MMA2 fp32-acc. 4-stage cp.async, 2 CTA/SM. Smem: 4 x 18432 B.
// ---------------------------------------------------------------------------
__global__ __launch_bounds__(256, 2) void attn_kernel()
{
    extern __shared__ char smb[];
    const int STG = 18432;

    const int bh = blockIdx.y;
    const int b  = bh >> 3, h = bh & 7;
    const int q0 = blockIdx.x * 128;
    const int tid = threadIdx.x;
    const int wid = tid >> 5, lane = tid & 31;
    const int qr = lane >> 2, qc = lane & 3;
    const int W0 = wid * 16;
    const uint32_t sbase = smem_u32(smb);
    uint32_t xb[4];
    #pragma unroll
    for (int i = 0; i < 4; i++) xb[i] = sbase + i*STG;

    // ---- stage Q' through buffer 0, load A-frags to registers ----
    #pragma unroll
    for (int i = 0; i < 4; i++) {
        int f = tid + 256*i;
        int r = f >> 3, c8 = (f & 7) << 3;
        cp16(xb[0] + (uint32_t)(r*72 + c8)*2,
             &g_Qh[((size_t)bh*SS + q0 + r)*DD + c8]);
    }
    CP_COMMIT(); CP_WAIT0();
    __syncthreads();
    uint32_t qa[4][4];
    #pragma unroll
    for (int t = 0; t < 4; t++)
        ldmx4(qa[t], xb[0] +
            ((uint32_t)(W0 + (lane & 15))*72 + t*16 + (lane >> 4)*8)*2);
    __syncthreads();    // all Q reads done before pipeline overwrites xb[0]

    load_x_stage(xb[0], bh, 0, tid); CP_COMMIT();
    load_x_stage(xb[1], bh, 1, tid); CP_COMMIT();
    load_x_stage(xb[2], bh, 2, tid); CP_COMMIT();

    float o[8][4];
    float lsA = 0.f, lsB = 0.f;       // fp32 row-sum accumulators (qr, qr+8)
    #pragma unroll
    for (int n = 0; n < 8; n++)
        #pragma unroll
        for (int r = 0; r < 4; r++) o[n][r] = 0.f;

    for (int kt = 0; kt < SS/128; kt++) {
        const int cur = kt & 3;
        CP_WAIT2();
        __syncthreads();
        if (kt + 3 < SS/128) {
            load_x_stage(xb[(kt + 3) & 3], bh, kt+3, tid);
            CP_COMMIT();
        }

        #pragma unroll
        for (int jc = 0; jc < 8; jc++) {
            const uint32_t rowaddr = xb[cur] +
                ((uint32_t)(jc*16 + (lane & 15))*72 + (lane >> 4)*8)*2;
            // ---- MMA1: S(16q x 16j) over k=64, f16 acc, 4 indep chains ----
            uint32_t sA0[2] = {0u,0u}, sA1[2] = {0u,0u};
            uint32_t sB0[2] = {0u,0u}, sB1[2] = {0u,0u};
            {
                uint32_t kr[4];
                ldmx4(kr, rowaddr);
                mma_f16f16(sA0, qa[0], kr[0], kr[2]);
                mma_f16f16(sB0, qa[0], kr[1], kr[3]);
                ldmx4(kr, rowaddr + 32);
                mma_f16f16(sA1, qa[1], kr[0], kr[2]);
                mma_f16f16(sB1, qa[1], kr[1], kr[3]);
                ldmx4(kr, rowaddr + 64);
                mma_f16f16(sA0, qa[2], kr[0], kr[2]);
                mma_f16f16(sB0, qa[2], kr[1], kr[3]);
                ldmx4(kr, rowaddr + 96);
                mma_f16f16(sA1, qa[3], kr[0], kr[2]);
                mma_f16f16(sB1, qa[3], kr[1], kr[3]);
            }
            // ---- P = ex2(S) (merge chains with HADD2 first) ----
            uint32_t pa[4];
            pa[0] = h2ex2(h2add(sA0[0], sA1[0]));
            pa[1] = h2ex2(h2add(sA0[1], sA1[1]));
            pa[2] = h2ex2(h2add(sB0[0], sB1[0]));
            pa[3] = h2ex2(h2add(sB0[1], sB1[1]));

            // ---- lsum on the fma pipe: rows qr / qr+8 partials ----
            {
                float2 ra = __half22float2(*(__half2*)&pa[0]);
                float2 rb = __half22float2(*(__half2*)&pa[2]);
                lsA += (ra.x + ra.y) + (rb.x + rb.y);
                float2 rc = __half22float2(*(__half2*)&pa[1]);
                float2 rd = __half22float2(*(__half2*)&pa[3]);
                lsB += (rc.x + rc.y) + (rd.x + rd.y);
            }

            // ---- MMA2 (fp32 acc): O += P x ----
            #pragma unroll
            for (int db = 0; db < 4; db++) {
                uint32_t vr[4];
                ldmx4t(vr, rowaddr + (uint32_t)(db*16)*2);
                mma_f16(o[db*2],   pa, vr[0], vr[1]);
                mma_f16(o[db*2+1], pa, vr[2], vr[3]);
            }
        }
    }

    // ---- epilogue: quad-reduce lsum, normalize, store fp16 ----
    #pragma unroll
    for (int off = 1; off < 4; off <<= 1) {
        lsA += __shfl_xor_sync(0xffffffffu, lsA, off);
        lsB += __shfl_xor_sync(0xffffffffu, lsB, off);
    }
    const float inv0 = 1.f / lsA;
    const float inv1 = 1.f / lsB;
    const int row0 = q0 + W0 + qr;
    __half* d0 = &g_AOh[((size_t)b*SS + row0)*EE + h*DD];
    __half* d1 = d0 + (size_t)8*EE;
    #pragma unroll
    for (int n = 0; n < 8; n++) {
        *(__half2*)&d0[n*8 + 2*qc] = __floats2half2_rn(o[n][0]*inv0, o[n][1]*inv0);
        *(__half2*)&d1[n*8 + 2*qc] = __floats2half2_rn(o[n][2]*inv1, o[n][3]*inv1);
    }
}

// ---------------------------------------------------------------------------
// Kernel 3: out = AO @ Wo2 + bo, fp16 mma, 3-stage cp.async, 2 CTA/SM.
// ---------------------------------------------------------------------------
__global__ __launch_bounds__(256, 2) void outproj_kernel(
    const float* __restrict__ bo, float* __restrict__ out)
{
    extern __shared__ char osmb[];
    const int STG = 18432 + 17408;
    const uint32_t sbase = smem_u32(osmb);
    uint32_t ab[3], wb[3];
    #pragma unroll
    for (int i = 0; i < 3; i++) {
        ab[i] = sbase + i*STG;
        wb[i] = ab[i] + 18432;
    }

    const int r0 = blockIdx.y * 128;
    const int e0 = blockIdx.x * 128;
    const int tid = threadIdx.x;
    const int wid = tid >> 5, lane = tid & 31;
    const int wq = wid >> 1, we = wid & 1;
    const int R0 = wq * 32, E0 = we * 64;
    const int qr = lane >> 2, qc = lane & 3;

    float c[2][8][4];
    #pragma unroll
    for (int m = 0; m < 2; m++)
        #pragma unroll
        for (int n = 0; n < 8; n++)
            #pragma unroll
            for (int r = 0; r < 4; r++) c[m][n][r] = 0.f;

    auto issue = [&](int st, int kc) {
        #pragma unroll
        for (int i = 0; i < 4; i++) {
            int f = tid + 256*i;
            int r = f >> 3, c8 = (f & 7) << 3;
            cp16(ab[st] + (uint32_t)(r*72 + c8)*2,
                 &g_AOh[(size_t)(r0 + r)*EE + kc*64 + c8]);
            int d = f >> 4, w8 = (f & 15) << 3;
            cp16(wb[st] + (uint32_t)(d*136 + w8)*2,
                 &g_WoT[(size_t)(kc*64 + d)*EE + e0 + w8]);
        }
        CP_COMMIT();
    };

    issue(0, 0);
    issue(1, 1);

    for (int kc = 0; kc < 8; kc++) {
        const int cur = kc % 3;
        CP_WAIT1();
        __syncthreads();
        if (kc + 2 < 8) issue((kc + 2) % 3, kc + 2);

        #pragma unroll
        for (int t = 0; t < 4; t++) {
            uint32_t qa[2][4];
            #pragma unroll
            for (int m = 0; m < 2; m++)
                ldmx4(qa[m], ab[cur] +
                    ((uint32_t)(R0 + 16*m + (lane & 15))*72 + t*16 + (lane >> 4)*8)*2);
            #pragma unroll
            for (int db = 0; db < 4; db++) {
                uint32_t wr[4];
                ldmx4t(wr, wb[cur] +
                    ((uint32_t)(t*16 + (lane & 15))*136 + E0 + db*16 + (lane >> 4)*8)*2);
                mma_f16(c[0][db*2],   qa[0], wr[0], wr[1]);
                mma_f16(c[1][db*2],   qa[1], wr[0], wr[1]);
                mma_f16(c[0][db*2+1], qa[0], wr[2], wr[3]);
                mma_f16(c[1][db*2+1], qa[1], wr[2], wr[3]);
            }
        }
    }

    #pragma unroll
    for (int m = 0; m < 2; m++)
        #pragma unroll
        for (int n = 0; n < 8; n++) {
            int e = e0 + E0 + n*8 + qc*2;
            float b0 = bo[e], b1 = bo[e+1];
            int r = r0 + R0 + 16*m + qr;
            *(float2*)&out[(size_t)r*EE + e] =
                make_float2(c[m][n][0] + b0, c[m][n][1] + b1);
            *(float2*)&out[(size_t)(r+8)*EE + e] =
                make_float2(c[m][n][2] + b0, c[m][n][3] + b1);
        }
}

// ---------------------------------------------------------------------------
extern "C" void kernel_launch(void* const* d_in, const int* in_sizes, int n_in,
                              void* d_out, int out_size)
{
    const float* queries = (const float*)d_in[0];
    // d_in[1]/d_in[2] unused: reference derives K and V from queries.
    const float* Wq = (const float*)d_in[3];
    const float* Wk = (const float*)d_in[4];
    const float* Wv = (const float*)d_in[5];
    const float* Wo = (const float*)d_in[6];
    const float* bo = (const float*)d_in[7];
    float* out = (float*)d_out;

    const int ATTN_SMEM = 4 * 18432;             // 73728 B
    const int OP_SMEM   = 3 * (18432 + 17408);   // 107520 B
    cudaFuncSetAttribute(attn_kernel,
        cudaFuncAttributeMaxDynamicSharedMemorySize, ATTN_SMEM);
    cudaFuncSetAttribute(outproj_kernel,
        cudaFuncAttributeMaxDynamicSharedMemorySize, OP_SMEM);

    m_prep_kernel<<<16, 256>>>(Wq, Wk);
    wo2_prep_kernel<<<dim3(EE/64, HH), 256>>>(Wv, Wo);
    proj_kernel<<<dim3(SS/128, BH), 256>>>(queries);
    attn_kernel<<<dim3(SS/128, BH), 256, ATTN_SMEM>>>();
    outproj_kernel<<<dim3(EE/128, (BB*SS)/128), 256, OP_SMEM>>>(bo, out);
}

// round 15
// speedup vs baseline: 1.1465x; 1.0569x over previous
#include <cuda_runtime.h>
#include <cuda_fp16.h>
#include <cstdint>

#define BB 4
#define SS 2048
#define HH 8
#define DD 64
#define EE 512
#define BH (BB*HH)

// Scratch (allocation-free: __device__ globals)
__device__ __half g_Qh[BH*SS*DD];   // [b,h,s,d] Q' = x @ (C*Wq^T Wk), fp16
__device__ __half g_Xh[BH*SS*DD];   // [b,h,s,d] raw x fp16 (serves as K and V)
__device__ __half g_MT[DD*DD];      // M^T: MT[b][a] = C*sum_e Wq[e][a]Wk[e][b]
__device__ __half g_AOh[BB*SS*EE];  // attention output fp16 (pre-Wo2)
__device__ __half g_WoT[EE*EE];     // Wo2[k][e] fp16 (Wv folded into Wo)

// ============================ helpers ======================================
__device__ __forceinline__ uint32_t smem_u32(const void* p) {
    uint32_t a;
    asm("{ .reg .u64 t; cvta.to.shared.u64 t, %1; cvt.u32.u64 %0, t; }"
        : "=r"(a) : "l"(p));
    return a;
}
__device__ __forceinline__ uint32_t h2ex2(uint32_t x) {
    uint32_t r;
    asm("ex2.approx.f16x2 %0, %1;" : "=r"(r) : "r"(x));
    return r;
}
__device__ __forceinline__ uint32_t h2add(uint32_t a, uint32_t b) {
    uint32_t r;
    asm("add.f16x2 %0, %1, %2;" : "=r"(r) : "r"(a), "r"(b));
    return r;
}
// fp16 inputs, fp32 accum
__device__ __forceinline__ void mma_f16(float* c, const uint32_t* a,
                                        uint32_t b0, uint32_t b1) {
    asm volatile("mma.sync.aligned.m16n8k16.row.col.f32.f16.f16.f32 "
        "{%0,%1,%2,%3}, {%4,%5,%6,%7}, {%8,%9}, {%0,%1,%2,%3};"
        : "+f"(c[0]), "+f"(c[1]), "+f"(c[2]), "+f"(c[3])
        : "r"(a[0]), "r"(a[1]), "r"(a[2]), "r"(a[3]), "r"(b0), "r"(b1));
}
// fp16 inputs, fp16 accum (C/D = 2 x b32 packed half2)
__device__ __forceinline__ void mma_f16f16(uint32_t* c, const uint32_t* a,
                                           uint32_t b0, uint32_t b1) {
    asm volatile("mma.sync.aligned.m16n8k16.row.col.f16.f16.f16.f16 "
        "{%0,%1}, {%2,%3,%4,%5}, {%6,%7}, {%0,%1};"
        : "+r"(c[0]), "+r"(c[1])
        : "r"(a[0]), "r"(a[1]), "r"(a[2]), "r"(a[3]), "r"(b0), "r"(b1));
}
__device__ __forceinline__ void ldmx4(uint32_t* r, uint32_t addr) {
    asm volatile("ldmatrix.sync.aligned.m8n8.x4.shared.b16 {%0,%1,%2,%3}, [%4];"
        : "=r"(r[0]), "=r"(r[1]), "=r"(r[2]), "=r"(r[3]) : "r"(addr));
}
__device__ __forceinline__ void ldmx4t(uint32_t* r, uint32_t addr) {
    asm volatile("ldmatrix.sync.aligned.m8n8.x4.trans.shared.b16 {%0,%1,%2,%3}, [%4];"
        : "=r"(r[0]), "=r"(r[1]), "=r"(r[2]), "=r"(r[3]) : "r"(addr));
}
__device__ __forceinline__ void cp16(uint32_t dst, const void* src) {
    asm volatile("cp.async.cg.shared.global [%0], [%1], 16;"
                 :: "r"(dst), "l"(src));
}
#define CP_COMMIT() asm volatile("cp.async.commit_group;" ::: "memory")
#define CP_WAIT0()  asm volatile("cp.async.wait_group 0;" ::: "memory")
#define CP_WAIT1()  asm volatile("cp.async.wait_group 1;" ::: "memory")

// ---------------------------------------------------------------------------
// Kernel P1: MT[b][a] = C * sum_e Wq[e][a] * Wk[e][b]. 16 blocks (parallel).
// ---------------------------------------------------------------------------
__global__ void m_prep_kernel(const float* __restrict__ Wq,
                              const float* __restrict__ Wk)
{
    __shared__ float sq[64*64], sk[64*64];
    const int tid = threadIdx.x;
    for (int i = tid; i < 4096; i += 256) { sq[i] = Wq[i]; sk[i] = Wk[i]; }
    __syncthreads();
    const int idx = blockIdx.x * 256 + tid;
    const int bq = idx >> 6, a = idx & 63;
    float acc = 0.f;
    #pragma unroll 8
    for (int e = 0; e < 64; e++) acc += sq[e*64 + a] * sk[e*64 + bq];
    g_MT[bq*64 + a] = __float2half(acc * 0.18033688011112042f);
}

// ---------------------------------------------------------------------------
// Kernel P2: Wo2[h*64+d][e] = sum_dp Wv[dp][d] * Wo[e][h*64+dp].
// grid (EE/64, HH), block 256. Thread owns fixed d + 16 e-outputs in regs.
// ---------------------------------------------------------------------------
__global__ void wo2_prep_kernel(const float* __restrict__ Wv,
                                const float* __restrict__ Wo)
{
    __shared__ float sv[64*64];      // Wv[dp][d]
    __shared__ float so[64][68];     // so[dp][e] = Wo[e0+e][h*64+dp]
    const int h = blockIdx.y, e0 = blockIdx.x * 64;
    const int tid = threadIdx.x;
    for (int i = tid; i < 4096; i += 256) {
        sv[i] = Wv[i];
        int e = i >> 6, dp = i & 63;
        so[dp][e] = Wo[(size_t)(e0 + e)*EE + h*64 + dp];
    }
    __syncthreads();
    const int d = tid >> 2;
    const int eb = (tid & 3) * 16;
    float acc[16];
    #pragma unroll
    for (int j = 0; j < 16; j++) acc[j] = 0.f;
    #pragma unroll 4
    for (int dp = 0; dp < 64; dp++) {
        float s = sv[dp*64 + d];
        #pragma unroll
        for (int j = 0; j < 16; j++) acc[j] += s * so[dp][eb + j];
    }
    #pragma unroll
    for (int j = 0; j < 16; j++)
        g_WoT[(size_t)(h*64 + d)*EE + e0 + eb + j] = __float2half(acc[j]);
}

// ---------------------------------------------------------------------------
// Kernel 1: x -> fp16 (g_Xh) and Q' = x @ M (g_Qh) via fp16 mma.
// ---------------------------------------------------------------------------
__global__ __launch_bounds__(256, 2) void proj_kernel(
    const float* __restrict__ X)
{
    __shared__ __half Xh[128*72];
    __shared__ __half Mh[64*72];
    const uint32_t xbase = smem_u32(Xh);

    const int bh = blockIdx.y;
    const int b  = bh >> 3, h = bh & 7;
    const int s0 = blockIdx.x * 128;
    const int tid = threadIdx.x;
    const int wid = tid >> 5, lane = tid & 31;
    const int wq = wid >> 1, we = wid & 1;
    const int R0 = wq * 32, E0 = we * 32;
    const int qr = lane >> 2, qc = lane & 3;

    #pragma unroll
    for (int i = 0; i < 8; i++) {
        int f = tid + 256*i;
        int r = f >> 4, c4 = (f & 15) << 2;
        float4 v = *(const float4*)&X[((size_t)b*SS + s0 + r)*EE + h*DD + c4];
        __half2 h01 = __floats2half2_rn(v.x, v.y);
        __half2 h23 = __floats2half2_rn(v.z, v.w);
        *(__half2*)&Xh[r*72 + c4]     = h01;
        *(__half2*)&Xh[r*72 + c4 + 2] = h23;
        __half* gx = &g_Xh[((size_t)bh*SS + s0 + r)*DD + c4];
        *(__half2*)&gx[0] = h01;
        *(__half2*)&gx[2] = h23;
    }
    #pragma unroll
    for (int i = 0; i < 2; i++) {
        int f = tid + 256*i;
        int r = f >> 3, c8 = (f & 7) << 3;
        *(uint4*)&Mh[r*72 + c8] = *(const uint4*)&g_MT[r*64 + c8];
    }
    __syncthreads();

    float c[2][4][4];
    #pragma unroll
    for (int m = 0; m < 2; m++)
        #pragma unroll
        for (int n = 0; n < 4; n++)
            #pragma unroll
            for (int r = 0; r < 4; r++) c[m][n][r] = 0.f;

    #pragma unroll
    for (int t = 0; t < 4; t++) {
        uint32_t qa[2][4];
        #pragma unroll
        for (int m = 0; m < 2; m++)
            ldmx4(qa[m], xbase +
                ((uint32_t)(R0 + 16*m + (lane & 15))*72 + t*16 + (lane >> 4)*8)*2);
        #pragma unroll
        for (int n = 0; n < 4; n++) {
            int jj = E0 + n*8 + qr;
            uint32_t b0 = *(const uint32_t*)&Mh[jj*72 + t*16 + qc*2];
            uint32_t b1 = *(const uint32_t*)&Mh[jj*72 + t*16 + qc*2 + 8];
            mma_f16(c[0][n], qa[0], b0, b1);
            mma_f16(c[1][n], qa[1], b0, b1);
        }
    }

    #pragma unroll
    for (int m = 0; m < 2; m++)
        #pragma unroll
        for (int n = 0; n < 4; n++) {
            int e = E0 + n*8 + qc*2;
            int s = s0 + R0 + 16*m + qr;
            *(__half2*)&g_Qh[((size_t)bh*SS + s)*DD + e] =
                __floats2half2_rn(c[m][n][0], c[m][n][1]);
            *(__half2*)&g_Qh[((size_t)bh*SS + s+8)*DD + e] =
                __floats2half2_rn(c[m][n][2], c[m][n][3]);
        }
}

// ---------------------------------------------------------------------------
// Attention stage loader (128-thread CTA): cp.async one x tile [128][72].
// ---------------------------------------------------------------------------
__device__ __forceinline__ void load_x_stage(
    uint32_t xaddr, int bh, int kt, int tid)
{
    #pragma unroll
    for (int i = 0; i < 8; i++) {
        int f = tid + 128*i;
        int r = f >> 3, c8 = (f & 7) << 3;
        cp16(xaddr + (uint32_t)(r*72 + c8)*2,
             &g_Xh[((size_t)bh*SS + (size_t)kt*128 + r)*DD + c8]);
    }
}

// ---------------------------------------------------------------------------
// Kernel 2: attention, K = V = x single tile. NEW GRANULARITY:
// 128 threads / 4 warps per CTA, 64 q-rows per CTA, 4 CTAs/SM — same warp
// tile (16q x full 128j) and identical per-warp mainloop as R14, but
// barriers span 4 warps and each SM holds 4 independent sync domains so
// one CTA's per-kt barrier/cp-wait overlaps another's MMA stream.
// MMA1 f16-acc 4 chains; P = ex2(S); lsum on fma pipe; MMA2 fp32-acc.
// 3-stage cp.async. Smem: 3 x 18432 = 55296 B/CTA.
// ---------------------------------------------------------------------------
__global__ __launch_bounds__(128, 4) void attn_kernel()
{
    extern __shared__ char smb[];
    const int STG = 18432;

    const int bh = blockIdx.y;
    const int b  = bh >> 3, h = bh & 7;
    const int q0 = blockIdx.x * 64;
    const int tid = threadIdx.x;
    const int wid = tid >> 5, lane = tid & 31;
    const int qr = lane >> 2, qc = lane & 3;
    const int W0 = wid * 16;
    const uint32_t sbase = smem_u32(smb);
    uint32_t xb[3];
    #pragma unroll
    for (int i = 0; i < 3; i++) xb[i] = sbase + i*STG;

    // ---- stage Q' (64 rows) through buffer 0, load A-frags to registers ----
    #pragma unroll
    for (int i = 0; i < 4; i++) {
        int f = tid + 128*i;
        int r = f >> 3, c8 = (f & 7) << 3;
        cp16(xb[0] + (uint32_t)(r*72 + c8)*2,
             &g_Qh[((size_t)bh*SS + q0 + r)*DD + c8]);
    }
    CP_COMMIT(); CP_WAIT0();
    __syncthreads();
    uint32_t qa[4][4];
    #pragma unroll
    for (int t = 0; t < 4; t++)
        ldmx4(qa[t], xb[0] +
            ((uint32_t)(W0 + (lane & 15))*72 + t*16 + (lane >> 4)*8)*2);
    __syncthreads();    // all Q reads done before pipeline overwrites xb[0]

    load_x_stage(xb[0], bh, 0, tid); CP_COMMIT();
    load_x_stage(xb[1], bh, 1, tid); CP_COMMIT();

    float o[8][4];
    float lsA = 0.f, lsB = 0.f;       // fp32 row-sum accumulators (qr, qr+8)
    #pragma unroll
    for (int n = 0; n < 8; n++)
        #pragma unroll
        for (int r = 0; r < 4; r++) o[n][r] = 0.f;

    for (int kt = 0; kt < SS/128; kt++) {
        const int cur = kt % 3;
        CP_WAIT1();
        __syncthreads();
        if (kt + 2 < SS/128) {
            load_x_stage(xb[(kt + 2) % 3], bh, kt+2, tid);
            CP_COMMIT();
        }

        #pragma unroll
        for (int jc = 0; jc < 8; jc++) {
            const uint32_t rowaddr = xb[cur] +
                ((uint32_t)(jc*16 + (lane & 15))*72 + (lane >> 4)*8)*2;
            // ---- MMA1: S(16q x 16j) over k=64, f16 acc, 4 indep chains ----
            uint32_t sA0[2] = {0u,0u}, sA1[2] = {0u,0u};
            uint32_t sB0[2] = {0u,0u}, sB1[2] = {0u,0u};
            {
                uint32_t kr[4];
                ldmx4(kr, rowaddr);
                mma_f16f16(sA0, qa[0], kr[0], kr[2]);
                mma_f16f16(sB0, qa[0], kr[1], kr[3]);
                ldmx4(kr, rowaddr + 32);
                mma_f16f16(sA1, qa[1], kr[0], kr[2]);
                mma_f16f16(sB1, qa[1], kr[1], kr[3]);
                ldmx4(kr, rowaddr + 64);
                mma_f16f16(sA0, qa[2], kr[0], kr[2]);
                mma_f16f16(sB0, qa[2], kr[1], kr[3]);
                ldmx4(kr, rowaddr + 96);
                mma_f16f16(sA1, qa[3], kr[0], kr[2]);
                mma_f16f16(sB1, qa[3], kr[1], kr[3]);
            }
            // ---- P = ex2(S) (merge chains with HADD2 first) ----
            uint32_t pa[4];
            pa[0] = h2ex2(h2add(sA0[0], sA1[0]));
            pa[1] = h2ex2(h2add(sA0[1], sA1[1]));
            pa[2] = h2ex2(h2add(sB0[0], sB1[0]));
            pa[3] = h2ex2(h2add(sB0[1], sB1[1]));

            // ---- lsum on the fma pipe: rows qr / qr+8 partials ----
            {
                float2 ra = __half22float2(*(__half2*)&pa[0]);
                float2 rb = __half22float2(*(__half2*)&pa[2]);
                lsA += (ra.x + ra.y) + (rb.x + rb.y);
                float2 rc = __half22float2(*(__half2*)&pa[1]);
                float2 rd = __half22float2(*(__half2*)&pa[3]);
                lsB += (rc.x + rc.y) + (rd.x + rd.y);
            }

            // ---- MMA2 (fp32 acc): O += P x ----
            #pragma unroll
            for (int db = 0; db < 4; db++) {
                uint32_t vr[4];
                ldmx4t(vr, rowaddr + (uint32_t)(db*16)*2);
                mma_f16(o[db*2],   pa, vr[0], vr[1]);
                mma_f16(o[db*2+1], pa, vr[2], vr[3]);
            }
        }
    }

    // ---- epilogue: quad-reduce lsum, normalize, store fp16 ----
    #pragma unroll
    for (int off = 1; off < 4; off <<= 1) {
        lsA += __shfl_xor_sync(0xffffffffu, lsA, off);
        lsB += __shfl_xor_sync(0xffffffffu, lsB, off);
    }
    const float inv0 = 1.f / lsA;
    const float inv1 = 1.f / lsB;
    const int row0 = q0 + W0 + qr;
    __half* d0 = &g_AOh[((size_t)b*SS + row0)*EE + h*DD];
    __half* d1 = d0 + (size_t)8*EE;
    #pragma unroll
    for (int n = 0; n < 8; n++) {
        *(__half2*)&d0[n*8 + 2*qc] = __floats2half2_rn(o[n][0]*inv0, o[n][1]*inv0);
        *(__half2*)&d1[n*8 + 2*qc] = __floats2half2_rn(o[n][2]*inv1, o[n][3]*inv1);
    }
}

// ---------------------------------------------------------------------------
// Kernel 3: out = AO @ Wo2 + bo, fp16 mma, 3-stage cp.async, 2 CTA/SM.
// ---------------------------------------------------------------------------
__global__ __launch_bounds__(256, 2) void outproj_kernel(
    const float* __restrict__ bo, float* __restrict__ out)
{
    extern __shared__ char osmb[];
    const int STG = 18432 + 17408;
    const uint32_t sbase = smem_u32(osmb);
    uint32_t ab[3], wb[3];
    #pragma unroll
    for (int i = 0; i < 3; i++) {
        ab[i] = sbase + i*STG;
        wb[i] = ab[i] + 18432;
    }

    const int r0 = blockIdx.y * 128;
    const int e0 = blockIdx.x * 128;
    const int tid = threadIdx.x;
    const int wid = tid >> 5, lane = tid & 31;
    const int wq = wid >> 1, we = wid & 1;
    const int R0 = wq * 32, E0 = we * 64;
    const int qr = lane >> 2, qc = lane & 3;

    float c[2][8][4];
    #pragma unroll
    for (int m = 0; m < 2; m++)
        #pragma unroll
        for (int n = 0; n < 8; n++)
            #pragma unroll
            for (int r = 0; r < 4; r++) c[m][n][r] = 0.f;

    auto issue = [&](int st, int kc) {
        #pragma unroll
        for (int i = 0; i < 4; i++) {
            int f = tid + 256*i;
            int r = f >> 3, c8 = (f & 7) << 3;
            cp16(ab[st] + (uint32_t)(r*72 + c8)*2,
                 &g_AOh[(size_t)(r0 + r)*EE + kc*64 + c8]);
            int d = f >> 4, w8 = (f & 15) << 3;
            cp16(wb[st] + (uint32_t)(d*136 + w8)*2,
                 &g_WoT[(size_t)(kc*64 + d)*EE + e0 + w8]);
        }
        CP_COMMIT();
    };

    issue(0, 0);
    issue(1, 1);

    for (int kc = 0; kc < 8; kc++) {
        const int cur = kc % 3;
        CP_WAIT1();
        __syncthreads();
        if (kc + 2 < 8) issue((kc + 2) % 3, kc + 2);

        #pragma unroll
        for (int t = 0; t < 4; t++) {
            uint32_t qa[2][4];
            #pragma unroll
            for (int m = 0; m < 2; m++)
                ldmx4(qa[m], ab[cur] +
                    ((uint32_t)(R0 + 16*m + (lane & 15))*72 + t*16 + (lane >> 4)*8)*2);
            #pragma unroll
            for (int db = 0; db < 4; db++) {
                uint32_t wr[4];
                ldmx4t(wr, wb[cur] +
                    ((uint32_t)(t*16 + (lane & 15))*136 + E0 + db*16 + (lane >> 4)*8)*2);
                mma_f16(c[0][db*2],   qa[0], wr[0], wr[1]);
                mma_f16(c[1][db*2],   qa[1], wr[0], wr[1]);
                mma_f16(c[0][db*2+1], qa[0], wr[2], wr[3]);
                mma_f16(c[1][db*2+1], qa[1], wr[2], wr[3]);
            }
        }
    }

    #pragma unroll
    for (int m = 0; m < 2; m++)
        #pragma unroll
        for (int n = 0; n < 8; n++) {
            int e = e0 + E0 + n*8 + qc*2;
            float b0 = bo[e], b1 = bo[e+1];
            int r = r0 + R0 + 16*m + qr;
            *(float2*)&out[(size_t)r*EE + e] =
                make_float2(c[m][n][0] + b0, c[m][n][1] + b1);
            *(float2*)&out[(size_t)(r+8)*EE + e] =
                make_float2(c[m][n][2] + b0, c[m][n][3] + b1);
        }
}

// ---------------------------------------------------------------------------
extern "C" void kernel_launch(void* const* d_in, const int* in_sizes, int n_in,
                              void* d_out, int out_size)
{
    const float* queries = (const float*)d_in[0];
    // d_in[1]/d_in[2] unused: reference derives K and V from queries.
    const float* Wq = (const float*)d_in[3];
    const float* Wk = (const float*)d_in[4];
    const float* Wv = (const float*)d_in[5];
    const float* Wo = (const float*)d_in[6];
    const float* bo = (const float*)d_in[7];
    float* out = (float*)d_out;

    const int ATTN_SMEM = 3 * 18432;             // 55296 B (4 CTAs/SM)
    const int OP_SMEM   = 3 * (18432 + 17408);   // 107520 B
    cudaFuncSetAttribute(attn_kernel,
        cudaFuncAttributeMaxDynamicSharedMemorySize, ATTN_SMEM);
    cudaFuncSetAttribute(outproj_kernel,
        cudaFuncAttributeMaxDynamicSharedMemorySize, OP_SMEM);

    m_prep_kernel<<<16, 256>>>(Wq, Wk);
    wo2_prep_kernel<<<dim3(EE/64, HH), 256>>>(Wv, Wo);
    proj_kernel<<<dim3(SS/128, BH), 256>>>(queries);
    attn_kernel<<<dim3(SS/64, BH), 128, ATTN_SMEM>>>();
    outproj_kernel<<<dim3(EE/128, (BB*SS)/128), 256, OP_SMEM>>>(bo, out);
}

// round 16
// speedup vs baseline: 1.1671x; 1.0179x over previous
#include <cuda_runtime.h>
#include <cuda_fp16.h>
#include <cstdint>

#define BB 4
#define SS 2048
#define HH 8
#define DD 64
#define EE 512
#define BH (BB*HH)

// Scratch (allocation-free: __device__ globals)
__device__ __half g_Xh[BH*SS*DD];   // [b,h,s,d] raw x fp16 (K, V, and Q'-input)
__device__ __half g_MT[DD*DD];      // M^T: MT[b][a] = C*sum_e Wq[e][a]Wk[e][b]
__device__ __half g_AOh[BB*SS*EE];  // attention output fp16 (pre-Wo2)
__device__ __half g_WoT[EE*EE];     // Wo2[k][e] fp16 (Wv folded into Wo)

// ============================ helpers ======================================
__device__ __forceinline__ uint32_t smem_u32(const void* p) {
    uint32_t a;
    asm("{ .reg .u64 t; cvta.to.shared.u64 t, %1; cvt.u32.u64 %0, t; }"
        : "=r"(a) : "l"(p));
    return a;
}
__device__ __forceinline__ uint32_t h2ex2(uint32_t x) {
    uint32_t r;
    asm("ex2.approx.f16x2 %0, %1;" : "=r"(r) : "r"(x));
    return r;
}
__device__ __forceinline__ uint32_t h2add(uint32_t a, uint32_t b) {
    uint32_t r;
    asm("add.f16x2 %0, %1, %2;" : "=r"(r) : "r"(a), "r"(b));
    return r;
}
// fp16 inputs, fp32 accum
__device__ __forceinline__ void mma_f16(float* c, const uint32_t* a,
                                        uint32_t b0, uint32_t b1) {
    asm volatile("mma.sync.aligned.m16n8k16.row.col.f32.f16.f16.f32 "
        "{%0,%1,%2,%3}, {%4,%5,%6,%7}, {%8,%9}, {%0,%1,%2,%3};"
        : "+f"(c[0]), "+f"(c[1]), "+f"(c[2]), "+f"(c[3])
        : "r"(a[0]), "r"(a[1]), "r"(a[2]), "r"(a[3]), "r"(b0), "r"(b1));
}
// fp16 inputs, fp16 accum (C/D = 2 x b32 packed half2)
__device__ __forceinline__ void mma_f16f16(uint32_t* c, const uint32_t* a,
                                           uint32_t b0, uint32_t b1) {
    asm volatile("mma.sync.aligned.m16n8k16.row.col.f16.f16.f16.f16 "
        "{%0,%1}, {%2,%3,%4,%5}, {%6,%7}, {%0,%1};"
        : "+r"(c[0]), "+r"(c[1])
        : "r"(a[0]), "r"(a[1]), "r"(a[2]), "r"(a[3]), "r"(b0), "r"(b1));
}
__device__ __forceinline__ void ldmx4(uint32_t* r, uint32_t addr) {
    asm volatile("ldmatrix.sync.aligned.m8n8.x4.shared.b16 {%0,%1,%2,%3}, [%4];"
        : "=r"(r[0]), "=r"(r[1]), "=r"(r[2]), "=r"(r[3]) : "r"(addr));
}
__device__ __forceinline__ void ldmx4t(uint32_t* r, uint32_t addr) {
    asm volatile("ldmatrix.sync.aligned.m8n8.x4.trans.shared.b16 {%0,%1,%2,%3}, [%4];"
        : "=r"(r[0]), "=r"(r[1]), "=r"(r[2]), "=r"(r[3]) : "r"(addr));
}
__device__ __forceinline__ uint32_t pack_h2(float lo, float hi) {
    __half2 h = __floats2half2_rn(lo, hi);
    return *(uint32_t*)&h;
}
__device__ __forceinline__ void cp16(uint32_t dst, const void* src) {
    asm volatile("cp.async.cg.shared.global [%0], [%1], 16;"
                 :: "r"(dst), "l"(src));
}
#define CP_COMMIT() asm volatile("cp.async.commit_group;" ::: "memory")
#define CP_WAIT0()  asm volatile("cp.async.wait_group 0;" ::: "memory")
#define CP_WAIT1()  asm volatile("cp.async.wait_group 1;" ::: "memory")

// ---------------------------------------------------------------------------
// Kernel P1: MT[b][a] = C * sum_e Wq[e][a] * Wk[e][b]. 16 blocks (parallel).
// ---------------------------------------------------------------------------
__global__ void m_prep_kernel(const float* __restrict__ Wq,
                              const float* __restrict__ Wk)
{
    __shared__ float sq[64*64], sk[64*64];
    const int tid = threadIdx.x;
    for (int i = tid; i < 4096; i += 256) { sq[i] = Wq[i]; sk[i] = Wk[i]; }
    __syncthreads();
    const int idx = blockIdx.x * 256 + tid;
    const int bq = idx >> 6, a = idx & 63;
    float acc = 0.f;
    #pragma unroll 8
    for (int e = 0; e < 64; e++) acc += sq[e*64 + a] * sk[e*64 + bq];
    g_MT[bq*64 + a] = __float2half(acc * 0.18033688011112042f);
}

// ---------------------------------------------------------------------------
// Kernel P2: Wo2[h*64+d][e] = sum_dp Wv[dp][d] * Wo[e][h*64+dp].
// grid (EE/64, HH), block 256. Thread owns fixed d + 16 e-outputs in regs.
// ---------------------------------------------------------------------------
__global__ void wo2_prep_kernel(const float* __restrict__ Wv,
                                const float* __restrict__ Wo)
{
    __shared__ float sv[64*64];      // Wv[dp][d]
    __shared__ float so[64][68];     // so[dp][e] = Wo[e0+e][h*64+dp]
    const int h = blockIdx.y, e0 = blockIdx.x * 64;
    const int tid = threadIdx.x;
    for (int i = tid; i < 4096; i += 256) {
        sv[i] = Wv[i];
        int e = i >> 6, dp = i & 63;
        so[dp][e] = Wo[(size_t)(e0 + e)*EE + h*64 + dp];
    }
    __syncthreads();
    const int d = tid >> 2;
    const int eb = (tid & 3) * 16;
    float acc[16];
    #pragma unroll
    for (int j = 0; j < 16; j++) acc[j] = 0.f;
    #pragma unroll 4
    for (int dp = 0; dp < 64; dp++) {
        float s = sv[dp*64 + d];
        #pragma unroll
        for (int j = 0; j < 16; j++) acc[j] += s * so[dp][eb + j];
    }
    #pragma unroll
    for (int j = 0; j < 16; j++)
        g_WoT[(size_t)(h*64 + d)*EE + e0 + eb + j] = __float2half(acc[j]);
}

// ---------------------------------------------------------------------------
// Kernel 1: pure convert x fp32 [b,s,E] -> g_Xh fp16 [bh][s][64].
// (Q' projection is now fused into the attention prologue.)
// ---------------------------------------------------------------------------
__global__ __launch_bounds__(256) void convert_kernel(
    const float* __restrict__ X)
{
    const int bh = blockIdx.y;
    const int b  = bh >> 3, h = bh & 7;
    const int s0 = blockIdx.x * 128;
    const int tid = threadIdx.x;
    #pragma unroll
    for (int i = 0; i < 8; i++) {
        int f = tid + 256*i;
        int r = f >> 4, c4 = (f & 15) << 2;
        float4 v = *(const float4*)&X[((size_t)b*SS + s0 + r)*EE + h*DD + c4];
        __half* gx = &g_Xh[((size_t)bh*SS + s0 + r)*DD + c4];
        *(__half2*)&gx[0] = __floats2half2_rn(v.x, v.y);
        *(__half2*)&gx[2] = __floats2half2_rn(v.z, v.w);
    }
}

// ---------------------------------------------------------------------------
// Attention stage loader (128-thread CTA): cp.async one x tile [128][72].
// ---------------------------------------------------------------------------
__device__ __forceinline__ void load_x_stage(
    uint32_t xaddr, int bh, int kt, int tid)
{
    #pragma unroll
    for (int i = 0; i < 8; i++) {
        int f = tid + 128*i;
        int r = f >> 3, c8 = (f & 7) << 3;
        cp16(xaddr + (uint32_t)(r*72 + c8)*2,
             &g_Xh[((size_t)bh*SS + (size_t)kt*128 + r)*DD + c8]);
    }
}

// ---------------------------------------------------------------------------
// Kernel 2: attention, K = V = x single tile, 128 thr / 4 warps / 64 q-rows
// per CTA, 4 CTAs/SM (R15's measured-best granularity). NEW: the prologue
// computes Q' = x @ M in-kernel (32 fp32-acc MMAs/warp, MT staged through
// the stage-2 buffer, B-access pattern identical to the old proj kernel),
// eliminating the proj kernel and the g_Qh round trip.
// Mainloop identical to R15: MMA1 f16-acc 4 chains; P = ex2(S); lsum on
// fma pipe; MMA2 fp32-acc. 3-stage cp.async. Smem: 3 x 18432 B.
// ---------------------------------------------------------------------------
__global__ __launch_bounds__(128, 4) void attn_kernel()
{
    extern __shared__ char smb[];
    const int STG = 18432;

    const int bh = blockIdx.y;
    const int b  = bh >> 3, h = bh & 7;
    const int q0 = blockIdx.x * 64;
    const int tid = threadIdx.x;
    const int wid = tid >> 5, lane = tid & 31;
    const int qr = lane >> 2, qc = lane & 3;
    const int W0 = wid * 16;
    const uint32_t sbase = smem_u32(smb);
    uint32_t xb[3];
    #pragma unroll
    for (int i = 0; i < 3; i++) xb[i] = sbase + i*STG;

    // ---- prologue: stage x q-tile (64 rows) -> xb[0], MT -> xb[2] ----
    #pragma unroll
    for (int i = 0; i < 4; i++) {
        int f = tid + 128*i;
        int r = f >> 3, c8 = (f & 7) << 3;
        cp16(xb[0] + (uint32_t)(r*72 + c8)*2,
             &g_Xh[((size_t)bh*SS + q0 + r)*DD + c8]);
        cp16(xb[2] + (uint32_t)(r*72 + c8)*2, &g_MT[r*64 + c8]);
    }
    CP_COMMIT(); CP_WAIT0();
    __syncthreads();

    // x A-frags for the Q' projection MMA
    uint32_t xa[4][4];
    #pragma unroll
    for (int t = 0; t < 4; t++)
        ldmx4(xa[t], xb[0] +
            ((uint32_t)(W0 + (lane & 15))*72 + t*16 + (lane >> 4)*8)*2);

    // Q' = x @ M  (fp32 acc, B indexing exactly as the old proj kernel),
    // packed straight into MMA1 A-fragments qa[t].
    const __half* MTs = (const __half*)(smb + 2*STG);
    uint32_t qa[4][4];
    #pragma unroll
    for (int t = 0; t < 4; t++) {
        float C0[4] = {0.f,0.f,0.f,0.f};
        float C1[4] = {0.f,0.f,0.f,0.f};
        #pragma unroll
        for (int kp = 0; kp < 4; kp++) {
            int j0 = (2*t)*8 + qr;
            uint32_t b0 = *(const uint32_t*)&MTs[j0*72 + kp*16 + qc*2];
            uint32_t b1 = *(const uint32_t*)&MTs[j0*72 + kp*16 + qc*2 + 8];
            mma_f16(C0, xa[kp], b0, b1);
            int j1 = (2*t+1)*8 + qr;
            uint32_t b2 = *(const uint32_t*)&MTs[j1*72 + kp*16 + qc*2];
            uint32_t b3 = *(const uint32_t*)&MTs[j1*72 + kp*16 + qc*2 + 8];
            mma_f16(C1, xa[kp], b2, b3);
        }
        qa[t][0] = pack_h2(C0[0], C0[1]);
        qa[t][1] = pack_h2(C0[2], C0[3]);
        qa[t][2] = pack_h2(C1[0], C1[1]);
        qa[t][3] = pack_h2(C1[2], C1[3]);
    }
    __syncthreads();    // x + MT reads done before pipeline overwrites

    load_x_stage(xb[0], bh, 0, tid); CP_COMMIT();
    load_x_stage(xb[1], bh, 1, tid); CP_COMMIT();

    float o[8][4];
    float lsA = 0.f, lsB = 0.f;       // fp32 row-sum accumulators (qr, qr+8)
    #pragma unroll
    for (int n = 0; n < 8; n++)
        #pragma unroll
        for (int r = 0; r < 4; r++) o[n][r] = 0.f;

    for (int kt = 0; kt < SS/128; kt++) {
        const int cur = kt % 3;
        CP_WAIT1();
        __syncthreads();
        if (kt + 2 < SS/128) {
            load_x_stage(xb[(kt + 2) % 3], bh, kt+2, tid);
            CP_COMMIT();
        }

        #pragma unroll
        for (int jc = 0; jc < 8; jc++) {
            const uint32_t rowaddr = xb[cur] +
                ((uint32_t)(jc*16 + (lane & 15))*72 + (lane >> 4)*8)*2;
            // ---- MMA1: S(16q x 16j) over k=64, f16 acc, 4 indep chains ----
            uint32_t sA0[2] = {0u,0u}, sA1[2] = {0u,0u};
            uint32_t sB0[2] = {0u,0u}, sB1[2] = {0u,0u};
            {
                uint32_t kr[4];
                ldmx4(kr, rowaddr);
                mma_f16f16(sA0, qa[0], kr[0], kr[2]);
                mma_f16f16(sB0, qa[0], kr[1], kr[3]);
                ldmx4(kr, rowaddr + 32);
                mma_f16f16(sA1, qa[1], kr[0], kr[2]);
                mma_f16f16(sB1, qa[1], kr[1], kr[3]);
                ldmx4(kr, rowaddr + 64);
                mma_f16f16(sA0, qa[2], kr[0], kr[2]);
                mma_f16f16(sB0, qa[2], kr[1], kr[3]);
                ldmx4(kr, rowaddr + 96);
                mma_f16f16(sA1, qa[3], kr[0], kr[2]);
                mma_f16f16(sB1, qa[3], kr[1], kr[3]);
            }
            // ---- P = ex2(S) (merge chains with HADD2 first) ----
            uint32_t pa[4];
            pa[0] = h2ex2(h2add(sA0[0], sA1[0]));
            pa[1] = h2ex2(h2add(sA0[1], sA1[1]));
            pa[2] = h2ex2(h2add(sB0[0], sB1[0]));
            pa[3] = h2ex2(h2add(sB0[1], sB1[1]));

            // ---- lsum on the fma pipe: rows qr / qr+8 partials ----
            {
                float2 ra = __half22float2(*(__half2*)&pa[0]);
                float2 rb = __half22float2(*(__half2*)&pa[2]);
                lsA += (ra.x + ra.y) + (rb.x + rb.y);
                float2 rc = __half22float2(*(__half2*)&pa[1]);
                float2 rd = __half22float2(*(__half2*)&pa[3]);
                lsB += (rc.x + rc.y) + (rd.x + rd.y);
            }

            // ---- MMA2 (fp32 acc): O += P x ----
            #pragma unroll
            for (int db = 0; db < 4; db++) {
                uint32_t vr[4];
                ldmx4t(vr, rowaddr + (uint32_t)(db*16)*2);
                mma_f16(o[db*2],   pa, vr[0], vr[1]);
                mma_f16(o[db*2+1], pa, vr[2], vr[3]);
            }
        }
    }

    // ---- epilogue: quad-reduce lsum, normalize, store fp16 ----
    #pragma unroll
    for (int off = 1; off < 4; off <<= 1) {
        lsA += __shfl_xor_sync(0xffffffffu, lsA, off);
        lsB += __shfl_xor_sync(0xffffffffu, lsB, off);
    }
    const float inv0 = 1.f / lsA;
    const float inv1 = 1.f / lsB;
    const int row0 = q0 + W0 + qr;
    __half* d0 = &g_AOh[((size_t)b*SS + row0)*EE + h*DD];
    __half* d1 = d0 + (size_t)8*EE;
    #pragma unroll
    for (int n = 0; n < 8; n++) {
        *(__half2*)&d0[n*8 + 2*qc] = __floats2half2_rn(o[n][0]*inv0, o[n][1]*inv0);
        *(__half2*)&d1[n*8 + 2*qc] = __floats2half2_rn(o[n][2]*inv1, o[n][3]*inv1);
    }
}

// ---------------------------------------------------------------------------
// Kernel 3: out = AO @ Wo2 + bo, fp16 mma, 3-stage cp.async, 2 CTA/SM.
// ---------------------------------------------------------------------------
__global__ __launch_bounds__(256, 2) void outproj_kernel(
    const float* __restrict__ bo, float* __restrict__ out)
{
    extern __shared__ char osmb[];
    const int STG = 18432 + 17408;
    const uint32_t sbase = smem_u32(osmb);
    uint32_t ab[3], wb[3];
    #pragma unroll
    for (int i = 0; i < 3; i++) {
        ab[i] = sbase + i*STG;
        wb[i] = ab[i] + 18432;
    }

    const int r0 = blockIdx.y * 128;
    const int e0 = blockIdx.x * 128;
    const int tid = threadIdx.x;
    const int wid = tid >> 5, lane = tid & 31;
    const int wq = wid >> 1, we = wid & 1;
    const int R0 = wq * 32, E0 = we * 64;
    const int qr = lane >> 2, qc = lane & 3;

    float c[2][8][4];
    #pragma unroll
    for (int m = 0; m < 2; m++)
        #pragma unroll
        for (int n = 0; n < 8; n++)
            #pragma unroll
            for (int r = 0; r < 4; r++) c[m][n][r] = 0.f;

    auto issue = [&](int st, int kc) {
        #pragma unroll
        for (int i = 0; i < 4; i++) {
            int f = tid + 256*i;
            int r = f >> 3, c8 = (f & 7) << 3;
            cp16(ab[st] + (uint32_t)(r*72 + c8)*2,
                 &g_AOh[(size_t)(r0 + r)*EE + kc*64 + c8]);
            int d = f >> 4, w8 = (f & 15) << 3;
            cp16(wb[st] + (uint32_t)(d*136 + w8)*2,
                 &g_WoT[(size_t)(kc*64 + d)*EE + e0 + w8]);
        }
        CP_COMMIT();
    };

    issue(0, 0);
    issue(1, 1);

    for (int kc = 0; kc < 8; kc++) {
        const int cur = kc % 3;
        CP_WAIT1();
        __syncthreads();
        if (kc + 2 < 8) issue((kc + 2) % 3, kc + 2);

        #pragma unroll
        for (int t = 0; t < 4; t++) {
            uint32_t qa[2][4];
            #pragma unroll
            for (int m = 0; m < 2; m++)
                ldmx4(qa[m], ab[cur] +
                    ((uint32_t)(R0 + 16*m + (lane & 15))*72 + t*16 + (lane >> 4)*8)*2);
            #pragma unroll
            for (int db = 0; db < 4; db++) {
                uint32_t wr[4];
                ldmx4t(wr, wb[cur] +
                    ((uint32_t)(t*16 + (lane & 15))*136 + E0 + db*16 + (lane >> 4)*8)*2);
                mma_f16(c[0][db*2],   qa[0], wr[0], wr[1]);
                mma_f16(c[1][db*2],   qa[1], wr[0], wr[1]);
                mma_f16(c[0][db*2+1], qa[0], wr[2], wr[3]);
                mma_f16(c[1][db*2+1], qa[1], wr[2], wr[3]);
            }
        }
    }

    #pragma unroll
    for (int m = 0; m < 2; m++)
        #pragma unroll
        for (int n = 0; n < 8; n++) {
            int e = e0 + E0 + n*8 + qc*2;
            float b0 = bo[e], b1 = bo[e+1];
            int r = r0 + R0 + 16*m + qr;
            *(float2*)&out[(size_t)r*EE + e] =
                make_float2(c[m][n][0] + b0, c[m][n][1] + b1);
            *(float2*)&out[(size_t)(r+8)*EE + e] =
                make_float2(c[m][n][2] + b0, c[m][n][3] + b1);
        }
}

// ---------------------------------------------------------------------------
extern "C" void kernel_launch(void* const* d_in, const int* in_sizes, int n_in,
                              void* d_out, int out_size)
{
    const float* queries = (const float*)d_in[0];
    // d_in[1]/d_in[2] unused: reference derives K and V from queries.
    const float* Wq = (const float*)d_in[3];
    const float* Wk = (const float*)d_in[4];
    const float* Wv = (const float*)d_in[5];
    const float* Wo = (const float*)d_in[6];
    const float* bo = (const float*)d_in[7];
    float* out = (float*)d_out;

    const int ATTN_SMEM = 3 * 18432;             // 55296 B (4 CTAs/SM)
    const int OP_SMEM   = 3 * (18432 + 17408);   // 107520 B
    cudaFuncSetAttribute(attn_kernel,
        cudaFuncAttributeMaxDynamicSharedMemorySize, ATTN_SMEM);
    cudaFuncSetAttribute(outproj_kernel,
        cudaFuncAttributeMaxDynamicSharedMemorySize, OP_SMEM);

    m_prep_kernel<<<16, 256>>>(Wq, Wk);
    wo2_prep_kernel<<<dim3(EE/64, HH), 256>>>(Wv, Wo);
    convert_kernel<<<dim3(SS/128, BH), 256>>>(queries);
    attn_kernel<<<dim3(SS/64, BH), 128, ATTN_SMEM>>>();
    outproj_kernel<<<dim3(EE/128, (BB*SS)/128), 256, OP_SMEM>>>(bo, out);
}